// round 14
// baseline (speedup 1.0000x reference)
#include <cuda_runtime.h>
#include <cuda_fp16.h>
#include <cstdint>
#include <cstddef>

#define NN   100000
#define EE   1600000
#define DINC 128
#define DHC  128
#define DOUTC 64

// ---------------- scratch (no allocations allowed) ----------------
__device__ int   g_deg[NN];          // zero-initialized; reset to 0 by scan_local each launch
__device__ float g_dinv[NN];
__device__ int   g_rowptr[NN + 1];
__device__ int   g_cursor[NN];
__device__ int2  g_edge[EE];                     // {src, wgt-bits}, grouped by dst
__device__ float g_hbuf[(size_t)NN * DHC];       // fp32 hidden (gemm input)
__device__ __align__(16) short g_qtab[(size_t)NN * DHC];  // int16 gather table
__device__ float g_scl[NN];                      // per-row dequant scale

#define SCAN_TPB 1024
#define SCAN_NBLK ((NN + SCAN_TPB - 1) / SCAN_TPB)   // 98
__device__ int g_bsum[128];

// ---------------- graph build ----------------
__global__ void count_deg_kernel(const int* __restrict__ dst) {
    int e = blockIdx.x * blockDim.x + threadIdx.x;
    if (e < EE) atomicAdd(&g_deg[dst[e]], 1);
}

// local exclusive scan of indegree + block totals + dinv; resets g_deg for next replay
__global__ void scan_local_kernel() {
    __shared__ int ws[32];
    int tid  = threadIdx.x;
    int lane = tid & 31;
    int wid  = tid >> 5;
    int i = blockIdx.x * SCAN_TPB + tid;
    int v = 0;
    if (i < NN) {
        v = g_deg[i];
        g_deg[i] = 0;                              // restore invariant for next launch
        g_dinv[i] = rsqrtf((float)(v + 1));        // +1 self loop
    }
    int x = v;
    #pragma unroll
    for (int o = 1; o < 32; o <<= 1) {
        int y = __shfl_up_sync(0xFFFFFFFFu, x, o);
        if (lane >= o) x += y;
    }
    if (lane == 31) ws[wid] = x;
    __syncthreads();
    if (wid == 0) {
        int s = ws[lane];
        #pragma unroll
        for (int o = 1; o < 32; o <<= 1) {
            int y = __shfl_up_sync(0xFFFFFFFFu, s, o);
            if (lane >= o) s += y;
        }
        ws[lane] = s;
    }
    __syncthreads();
    int excl = (wid ? ws[wid - 1] : 0) + x - v;
    if (i < NN) g_rowptr[i] = excl;
    if (tid == 0) g_bsum[blockIdx.x] = ws[31];
}

// adds block offset (computed in-kernel from g_bsum) — scan_block fused away
__global__ void scan_add_kernel() {
    __shared__ int s_off;
    int t = threadIdx.x;
    if (t < 32) {
        int s = 0;
        for (int k = t; k < (int)blockIdx.x; k += 32) s += g_bsum[k];
        #pragma unroll
        for (int o = 16; o > 0; o >>= 1) s += __shfl_down_sync(0xFFFFFFFFu, s, o);
        if (t == 0) s_off = s;
    }
    __syncthreads();
    int i = blockIdx.x * SCAN_TPB + t;
    if (i < NN) {
        int r = g_rowptr[i] + s_off;
        g_rowptr[i] = r;
        g_cursor[i] = r;
    }
    if (i == 0) g_rowptr[NN] = EE;
}

__global__ void fill_csr_kernel(const int* __restrict__ src, const int* __restrict__ dst) {
    int e = blockIdx.x * blockDim.x + threadIdx.x;
    if (e < EE) {
        int s = src[e], d = dst[e];
        int slot = atomicAdd(&g_cursor[d], 1);
        float w = g_dinv[s] * g_dinv[d];
        g_edge[slot] = make_int2(s, __float_as_int(w));
    }
}

// ================= fp16-split mma.sync GEMM + int16-quant epilogue =================
__device__ __forceinline__ uint32_t s2u(const void* p) {
    uint32_t a;
    asm("{ .reg .u64 t; cvta.to.shared.u64 t, %1; cvt.u32.u64 %0, t; }" : "=r"(a) : "l"(p));
    return a;
}

#define LDSM4(r, a)                                                            \
    asm volatile("ldmatrix.sync.aligned.m8n8.x4.shared.b16 {%0,%1,%2,%3}, [%4];" \
                 : "=r"((r)[0]), "=r"((r)[1]), "=r"((r)[2]), "=r"((r)[3])      \
                 : "r"(a))

__device__ __forceinline__ void mma16816(float* c, const uint32_t* a, const uint32_t* b) {
    asm volatile(
        "mma.sync.aligned.m16n8k16.row.col.f32.f16.f16.f32 "
        "{%0,%1,%2,%3}, {%4,%5,%6,%7}, {%8,%9}, {%0,%1,%2,%3};"
        : "+f"(c[0]), "+f"(c[1]), "+f"(c[2]), "+f"(c[3])
        : "r"(a[0]), "r"(a[1]), "r"(a[2]), "r"(a[3]), "r"(b[0]), "r"(b[1]));
}

__device__ __forceinline__ uint32_t pack2(__half a, __half b) {
    __half2 h = __halves2half2(a, b);
    return *(uint32_t*)&h;
}

__device__ __forceinline__ short q16(float v, float inv) {
    int q = __float2int_rn(v * inv);
    q = max(-32767, min(32767, q));
    return (short)q;
}

template <int BN>
__global__ void __launch_bounds__(256, 2)
gemm_mma_kernel(const float* __restrict__ A, const float* __restrict__ W,
                short* __restrict__ QT, float* __restrict__ SCL) {
    constexpr int K = 128, KC = 64, RS = 72;
    constexpr int A_HI = 0;
    constexpr int A_LO = 128 * RS;
    constexpr int B_HI = 2 * 128 * RS;
    constexpr int B_LO = B_HI + BN * RS;
    constexpr int NT = BN / 16;
    constexpr int NP = NT / 2;

    extern __shared__ __half sm[];
    const uint32_t sb = s2u(sm);
    const int tid  = threadIdx.x;
    const int lane = tid & 31;
    const int warp = tid >> 5;
    const int wm = (warp & 3) * 32;
    const int wn = (warp >> 2) * (BN / 2);
    const int rowBase = blockIdx.x * 128;

    float acc[2][NT][4];
    #pragma unroll
    for (int mt = 0; mt < 2; mt++)
        #pragma unroll
        for (int nt = 0; nt < NT; nt++)
            #pragma unroll
            for (int q = 0; q < 4; q++) acc[mt][nt][q] = 0.0f;

    const int aRow = (lane & 7) + ((lane >> 3) & 1) * 8;
    const int aK   = (lane >> 4) * 8;
    const int bN   = (lane & 7) + ((lane >> 4) << 3);
    const int bK   = ((lane >> 3) & 1) * 8;

    for (int kc = 0; kc < 2; kc++) {
        #pragma unroll
        for (int l = 0; l < 8; l++) {
            int i = tid + l * 256;
            int r = i >> 4;
            int c = (i & 15) * 4;
            float4 v = make_float4(0.f, 0.f, 0.f, 0.f);
            int gr = rowBase + r;
            if (gr < NN) v = *(const float4*)(A + (size_t)gr * K + kc * KC + c);
            __half h0 = __float2half_rn(v.x), h1 = __float2half_rn(v.y);
            __half h2 = __float2half_rn(v.z), h3 = __float2half_rn(v.w);
            __half q0 = __float2half_rn(v.x - __half2float(h0));
            __half q1 = __float2half_rn(v.y - __half2float(h1));
            __half q2 = __float2half_rn(v.z - __half2float(h2));
            __half q3 = __float2half_rn(v.w - __half2float(h3));
            *(uint2*)&sm[A_HI + r * RS + c] = make_uint2(pack2(h0, h1), pack2(h2, h3));
            *(uint2*)&sm[A_LO + r * RS + c] = make_uint2(pack2(q0, q1), pack2(q2, q3));
        }
        #pragma unroll
        for (int l = 0; l < BN * KC / 4 / 256; l++) {
            int i  = tid + l * 256;
            int n  = i % BN;
            int k0 = (i / BN) * 4;
            float v0 = W[(size_t)(kc * KC + k0 + 0) * BN + n];
            float v1 = W[(size_t)(kc * KC + k0 + 1) * BN + n];
            float v2 = W[(size_t)(kc * KC + k0 + 2) * BN + n];
            float v3 = W[(size_t)(kc * KC + k0 + 3) * BN + n];
            __half h0 = __float2half_rn(v0), h1 = __float2half_rn(v1);
            __half h2 = __float2half_rn(v2), h3 = __float2half_rn(v3);
            __half q0 = __float2half_rn(v0 - __half2float(h0));
            __half q1 = __float2half_rn(v1 - __half2float(h1));
            __half q2 = __float2half_rn(v2 - __half2float(h2));
            __half q3 = __float2half_rn(v3 - __half2float(h3));
            *(uint2*)&sm[B_HI + n * RS + k0] = make_uint2(pack2(h0, h1), pack2(h2, h3));
            *(uint2*)&sm[B_LO + n * RS + k0] = make_uint2(pack2(q0, q1), pack2(q2, q3));
        }
        __syncthreads();

        #pragma unroll
        for (int ks = 0; ks < KC / 16; ks++) {
            uint32_t ah[2][4], al[2][4];
            #pragma unroll
            for (int mt = 0; mt < 2; mt++) {
                uint32_t off = (uint32_t)((wm + mt * 16 + aRow) * RS + ks * 16 + aK) * 2;
                LDSM4(ah[mt], sb + A_HI * 2 + off);
                LDSM4(al[mt], sb + A_LO * 2 + off);
            }
            #pragma unroll
            for (int np = 0; np < NP; np++) {
                uint32_t bh[4], bl[4];
                uint32_t off = (uint32_t)((wn + np * 16 + bN) * RS + ks * 16 + bK) * 2;
                LDSM4(bh, sb + B_HI * 2 + off);
                LDSM4(bl, sb + B_LO * 2 + off);
                #pragma unroll
                for (int mt = 0; mt < 2; mt++) {
                    mma16816(acc[mt][np * 2 + 0], ah[mt], &bh[0]);
                    mma16816(acc[mt][np * 2 + 0], ah[mt], &bl[0]);
                    mma16816(acc[mt][np * 2 + 0], al[mt], &bh[0]);
                    mma16816(acc[mt][np * 2 + 1], ah[mt], &bh[2]);
                    mma16816(acc[mt][np * 2 + 1], ah[mt], &bl[2]);
                    mma16816(acc[mt][np * 2 + 1], al[mt], &bh[2]);
                }
            }
        }
        __syncthreads();
    }

    // ---- epilogue: rowwise absmax -> int16 quantize ----
    const int g  = lane >> 2;
    const int tg = lane & 3;
    const int wHalf = warp >> 2;
    float* redmax = (float*)sm;

    float pm[2][2];
    #pragma unroll
    for (int mt = 0; mt < 2; mt++) {
        float m0 = 0.f, m1 = 0.f;
        #pragma unroll
        for (int nt = 0; nt < NT; nt++) {
            m0 = fmaxf(m0, fmaxf(fabsf(acc[mt][nt][0]), fabsf(acc[mt][nt][1])));
            m1 = fmaxf(m1, fmaxf(fabsf(acc[mt][nt][2]), fabsf(acc[mt][nt][3])));
        }
        #pragma unroll
        for (int o = 1; o <= 2; o <<= 1) {
            m0 = fmaxf(m0, __shfl_xor_sync(0xFFFFFFFFu, m0, o));
            m1 = fmaxf(m1, __shfl_xor_sync(0xFFFFFFFFu, m1, o));
        }
        pm[mt][0] = m0; pm[mt][1] = m1;
    }
    if (tg == 0) {
        #pragma unroll
        for (int mt = 0; mt < 2; mt++) {
            redmax[wHalf * 128 + wm + mt * 16 + g]     = pm[mt][0];
            redmax[wHalf * 128 + wm + mt * 16 + g + 8] = pm[mt][1];
        }
    }
    __syncthreads();

    #pragma unroll
    for (int mt = 0; mt < 2; mt++) {
        #pragma unroll
        for (int h = 0; h < 2; h++) {
            int r  = wm + mt * 16 + g + h * 8;
            int gr = rowBase + r;
            float fm  = fmaxf(redmax[r], redmax[128 + r]);
            float inv = (fm > 0.f) ? 32766.0f / fm : 0.0f;
            if (gr < NN) {
                if (wHalf == 0 && tg == 0) SCL[gr] = fm * (1.0f / 32766.0f);
                #pragma unroll
                for (int nt = 0; nt < NT; nt++) {
                    int col = wn + nt * 8 + tg * 2;
                    short2 qq = make_short2(q16(acc[mt][nt][h * 2 + 0], inv),
                                            q16(acc[mt][nt][h * 2 + 1], inv));
                    *(short2*)&QT[(size_t)gr * BN + col] = qq;
                }
            }
        }
    }
}

// -------- Aggregation v3: warp = G independent nodes, branch-free body --------
// D=128: G=2 nodes/warp, 16 lanes each own a full 256B row slice (16B/lane).
// D=64 : G=4 nodes/warp,  8 lanes each own a full 128B row slice (16B/lane).
// No cross-group reduction; short-degree groups pad with zero-weight clamped
// loads (SEL/IMNMX only — the loop body is fully convergent).
template <int D, bool RELU>
__global__ void agg_kernel(const short* __restrict__ QT,
                           const float* __restrict__ SCL,
                           const float* __restrict__ bias,
                           float* __restrict__ out) {
    constexpr int L = (D == 128) ? 16 : 8;   // lanes per node
    constexpr int G = 32 / L;                // nodes per warp
    int wgl  = (blockIdx.x * blockDim.x + threadIdx.x) >> 5;
    int lane = threadIdx.x & 31;
    int part = lane / L;
    int sub  = lane % L;
    int node = wgl * G + part;
    if (wgl * G >= NN) return;               // whole warp out of range
    int nodeC = min(node, NN - 1);
    int beg = g_rowptr[nodeC];
    int cnt = g_rowptr[nodeC + 1] - beg;
    if (node >= NN) cnt = 0;

    int mc = cnt;                             // warp-wide max degree
    #pragma unroll
    for (int o = L; o < 32; o <<= 1)
        mc = max(mc, __shfl_xor_sync(0xFFFFFFFFu, mc, o));

    float acc[8];
    {   // self loop (uniform across all groups)
        float di = g_dinv[nodeC];
        float ws = di * di * SCL[nodeC];
        union { uint4 u; short s[8]; } q;
        q.u = *(const uint4*)(QT + (size_t)nodeC * D + sub * 8);
        #pragma unroll
        for (int k = 0; k < 8; k++) acc[k] = ws * (float)q.s[k];
    }

    int last = beg + max(cnt - 1, 0);
    for (int t = 0; t < mc; t++) {
        int je = min(min(beg + t, last), EE - 1);   // always-valid slot
        int2 e = g_edge[je];
        float w = (t < cnt) ? __int_as_float(e.y) : 0.0f;
        int src = e.x;                               // valid node id even when padded
        float ws = w * SCL[src];
        union { uint4 u; short s[8]; } q;
        q.u = *(const uint4*)(QT + (size_t)src * D + sub * 8);
        #pragma unroll
        for (int k = 0; k < 8; k++) acc[k] += ws * (float)q.s[k];
    }

    if (node < NN) {
        float4 b0 = *(const float4*)(bias + sub * 8);
        float4 b1 = *(const float4*)(bias + sub * 8 + 4);
        float4 o0 = make_float4(acc[0] + b0.x, acc[1] + b0.y, acc[2] + b0.z, acc[3] + b0.w);
        float4 o1 = make_float4(acc[4] + b1.x, acc[5] + b1.y, acc[6] + b1.z, acc[7] + b1.w);
        if (RELU) {
            o0.x = fmaxf(o0.x, 0.f); o0.y = fmaxf(o0.y, 0.f);
            o0.z = fmaxf(o0.z, 0.f); o0.w = fmaxf(o0.w, 0.f);
            o1.x = fmaxf(o1.x, 0.f); o1.y = fmaxf(o1.y, 0.f);
            o1.z = fmaxf(o1.z, 0.f); o1.w = fmaxf(o1.w, 0.f);
        }
        *(float4*)(out + (size_t)node * D + sub * 8)     = o0;
        *(float4*)(out + (size_t)node * D + sub * 8 + 4) = o1;
    }
}

// ---------------- launch ----------------
extern "C" void kernel_launch(void* const* d_in, const int* in_sizes, int n_in,
                              void* d_out, int out_size) {
    const float* x  = (const float*)d_in[0];
    const float* W0 = (const float*)d_in[1];
    const float* b0 = (const float*)d_in[2];
    const float* W1 = (const float*)d_in[3];
    const float* b1 = (const float*)d_in[4];
    const float* W2 = (const float*)d_in[5];
    const float* b2 = (const float*)d_in[6];
    const int*  src = (const int*)d_in[7];
    const int*  dst = (const int*)d_in[8];
    float* out = (float*)d_out;

    float *hbuf = nullptr, *scl = nullptr;
    short* qtab = nullptr;
    cudaGetSymbolAddress((void**)&hbuf, g_hbuf);
    cudaGetSymbolAddress((void**)&scl, g_scl);
    cudaGetSymbolAddress((void**)&qtab, g_qtab);

    static cudaStream_t sB = nullptr;
    static cudaEvent_t evFork = nullptr, evBuild = nullptr;
    if (sB == nullptr) {
        cudaStreamCreateWithFlags(&sB, cudaStreamNonBlocking);
        cudaEventCreateWithFlags(&evFork, cudaEventDisableTiming);
        cudaEventCreateWithFlags(&evBuild, cudaEventDisableTiming);
    }

    const int SMEM128 = (2 * 128 + 2 * 128) * 72 * 2;   // 73728
    const int SMEM64  = (2 * 128 + 2 * 64)  * 72 * 2;   // 55296
    cudaFuncSetAttribute(gemm_mma_kernel<128>,
                         cudaFuncAttributeMaxDynamicSharedMemorySize, SMEM128);
    cudaFuncSetAttribute(gemm_mma_kernel<64>,
                         cudaFuncAttributeMaxDynamicSharedMemorySize, SMEM64);

    const int TPB = 256;
    const int edgeBlocks = (EE + TPB - 1) / TPB;
    const int gemmBlocks = (NN + 127) / 128;
    const int aggBlocks128 = ((NN / 2) * 32 + TPB - 1) / TPB;   // 2 nodes/warp
    const int aggBlocks64  = ((NN / 4) * 32 + TPB - 1) / TPB;   // 4 nodes/warp

    // ---- fork: CSR build on sB, concurrent with gemm0 ----
    cudaEventRecord(evFork, 0);
    cudaStreamWaitEvent(sB, evFork, 0);

    count_deg_kernel<<<edgeBlocks, TPB, 0, sB>>>(dst);     // g_deg==0 invariant
    scan_local_kernel<<<SCAN_NBLK, SCAN_TPB, 0, sB>>>();   // + resets g_deg
    scan_add_kernel<<<SCAN_NBLK, SCAN_TPB, 0, sB>>>();     // scan_block fused in
    fill_csr_kernel<<<edgeBlocks, TPB, 0, sB>>>(src, dst);
    cudaEventRecord(evBuild, sB);

    gemm_mma_kernel<128><<<gemmBlocks, TPB, SMEM128>>>(x, W0, qtab, scl);

    cudaStreamWaitEvent(0, evBuild, 0);

    agg_kernel<128, true><<<aggBlocks128, TPB>>>(qtab, scl, b0, hbuf);
    gemm_mma_kernel<128><<<gemmBlocks, TPB, SMEM128>>>(hbuf, W1, qtab, scl);
    agg_kernel<128, true><<<aggBlocks128, TPB>>>(qtab, scl, b1, hbuf);
    gemm_mma_kernel<64><<<gemmBlocks, TPB, SMEM64>>>(hbuf, W2, qtab, scl);
    agg_kernel<64, false><<<aggBlocks64, TPB>>>(qtab, scl, b2, out);
}

// round 15
// speedup vs baseline: 1.0050x; 1.0050x over previous
#include <cuda_runtime.h>
#include <cuda_fp16.h>
#include <cstdint>
#include <cstddef>

#define NN   100000
#define EE   1600000
#define DINC 128
#define DHC  128
#define DOUTC 64

// ---------------- scratch (no allocations allowed) ----------------
__device__ int   g_deg[NN];          // zero-initialized; reset to 0 by scan_local each launch
__device__ float g_dinv[NN];
__device__ int   g_rowptr[NN + 1];
__device__ int   g_cursor[NN];
__device__ int2  g_edge[EE];                     // {src, wgt-bits}, grouped by dst
__device__ float g_hbuf[(size_t)NN * DHC];       // fp32 hidden (gemm input)
__device__ __align__(16) short g_qtab[(size_t)NN * DHC];  // int16 gather table
__device__ float g_scl[NN];                      // per-row dequant scale

#define SCAN_TPB 1024
#define SCAN_NBLK ((NN + SCAN_TPB - 1) / SCAN_TPB)   // 98
__device__ int g_bsum[128];

// ---------------- graph build ----------------
__global__ void count_deg_kernel(const int* __restrict__ dst) {
    int e = blockIdx.x * blockDim.x + threadIdx.x;
    if (e < EE) atomicAdd(&g_deg[dst[e]], 1);
}

// local exclusive scan of indegree + block totals + dinv; resets g_deg for next replay
__global__ void scan_local_kernel() {
    __shared__ int ws[32];
    int tid  = threadIdx.x;
    int lane = tid & 31;
    int wid  = tid >> 5;
    int i = blockIdx.x * SCAN_TPB + tid;
    int v = 0;
    if (i < NN) {
        v = g_deg[i];
        g_deg[i] = 0;                              // restore invariant for next launch
        g_dinv[i] = rsqrtf((float)(v + 1));        // +1 self loop
    }
    int x = v;
    #pragma unroll
    for (int o = 1; o < 32; o <<= 1) {
        int y = __shfl_up_sync(0xFFFFFFFFu, x, o);
        if (lane >= o) x += y;
    }
    if (lane == 31) ws[wid] = x;
    __syncthreads();
    if (wid == 0) {
        int s = ws[lane];
        #pragma unroll
        for (int o = 1; o < 32; o <<= 1) {
            int y = __shfl_up_sync(0xFFFFFFFFu, s, o);
            if (lane >= o) s += y;
        }
        ws[lane] = s;
    }
    __syncthreads();
    int excl = (wid ? ws[wid - 1] : 0) + x - v;
    if (i < NN) g_rowptr[i] = excl;
    if (tid == 0) g_bsum[blockIdx.x] = ws[31];
}

// adds block offset (computed in-kernel from g_bsum) — scan_block fused away
__global__ void scan_add_kernel() {
    __shared__ int s_off;
    int t = threadIdx.x;
    if (t < 32) {
        int s = 0;
        for (int k = t; k < (int)blockIdx.x; k += 32) s += g_bsum[k];
        #pragma unroll
        for (int o = 16; o > 0; o >>= 1) s += __shfl_down_sync(0xFFFFFFFFu, s, o);
        if (t == 0) s_off = s;
    }
    __syncthreads();
    int i = blockIdx.x * SCAN_TPB + t;
    if (i < NN) {
        int r = g_rowptr[i] + s_off;
        g_rowptr[i] = r;
        g_cursor[i] = r;
    }
    if (i == 0) g_rowptr[NN] = EE;
}

__global__ void fill_csr_kernel(const int* __restrict__ src, const int* __restrict__ dst) {
    int e = blockIdx.x * blockDim.x + threadIdx.x;
    if (e < EE) {
        int s = src[e], d = dst[e];
        int slot = atomicAdd(&g_cursor[d], 1);
        float w = g_dinv[s] * g_dinv[d];
        g_edge[slot] = make_int2(s, __float_as_int(w));
    }
}

// ================= fp16-split mma.sync GEMM + int16-quant epilogue =================
__device__ __forceinline__ uint32_t s2u(const void* p) {
    uint32_t a;
    asm("{ .reg .u64 t; cvta.to.shared.u64 t, %1; cvt.u32.u64 %0, t; }" : "=r"(a) : "l"(p));
    return a;
}

#define LDSM4(r, a)                                                            \
    asm volatile("ldmatrix.sync.aligned.m8n8.x4.shared.b16 {%0,%1,%2,%3}, [%4];" \
                 : "=r"((r)[0]), "=r"((r)[1]), "=r"((r)[2]), "=r"((r)[3])      \
                 : "r"(a))

__device__ __forceinline__ void mma16816(float* c, const uint32_t* a, const uint32_t* b) {
    asm volatile(
        "mma.sync.aligned.m16n8k16.row.col.f32.f16.f16.f32 "
        "{%0,%1,%2,%3}, {%4,%5,%6,%7}, {%8,%9}, {%0,%1,%2,%3};"
        : "+f"(c[0]), "+f"(c[1]), "+f"(c[2]), "+f"(c[3])
        : "r"(a[0]), "r"(a[1]), "r"(a[2]), "r"(a[3]), "r"(b[0]), "r"(b[1]));
}

__device__ __forceinline__ uint32_t pack2(__half a, __half b) {
    __half2 h = __halves2half2(a, b);
    return *(uint32_t*)&h;
}

__device__ __forceinline__ short q16(float v, float inv) {
    int q = __float2int_rn(v * inv);
    q = max(-32767, min(32767, q));
    return (short)q;
}

template <int BN>
__global__ void __launch_bounds__(256, 2)
gemm_mma_kernel(const float* __restrict__ A, const float* __restrict__ W,
                short* __restrict__ QT, float* __restrict__ SCL) {
    constexpr int K = 128, KC = 64, RS = 72;
    constexpr int A_HI = 0;
    constexpr int A_LO = 128 * RS;
    constexpr int B_HI = 2 * 128 * RS;
    constexpr int B_LO = B_HI + BN * RS;
    constexpr int NT = BN / 16;
    constexpr int NP = NT / 2;

    extern __shared__ __half sm[];
    const uint32_t sb = s2u(sm);
    const int tid  = threadIdx.x;
    const int lane = tid & 31;
    const int warp = tid >> 5;
    const int wm = (warp & 3) * 32;
    const int wn = (warp >> 2) * (BN / 2);
    const int rowBase = blockIdx.x * 128;

    float acc[2][NT][4];
    #pragma unroll
    for (int mt = 0; mt < 2; mt++)
        #pragma unroll
        for (int nt = 0; nt < NT; nt++)
            #pragma unroll
            for (int q = 0; q < 4; q++) acc[mt][nt][q] = 0.0f;

    const int aRow = (lane & 7) + ((lane >> 3) & 1) * 8;
    const int aK   = (lane >> 4) * 8;
    const int bN   = (lane & 7) + ((lane >> 4) << 3);
    const int bK   = ((lane >> 3) & 1) * 8;

    for (int kc = 0; kc < 2; kc++) {
        #pragma unroll
        for (int l = 0; l < 8; l++) {
            int i = tid + l * 256;
            int r = i >> 4;
            int c = (i & 15) * 4;
            float4 v = make_float4(0.f, 0.f, 0.f, 0.f);
            int gr = rowBase + r;
            if (gr < NN) v = *(const float4*)(A + (size_t)gr * K + kc * KC + c);
            __half h0 = __float2half_rn(v.x), h1 = __float2half_rn(v.y);
            __half h2 = __float2half_rn(v.z), h3 = __float2half_rn(v.w);
            __half q0 = __float2half_rn(v.x - __half2float(h0));
            __half q1 = __float2half_rn(v.y - __half2float(h1));
            __half q2 = __float2half_rn(v.z - __half2float(h2));
            __half q3 = __float2half_rn(v.w - __half2float(h3));
            *(uint2*)&sm[A_HI + r * RS + c] = make_uint2(pack2(h0, h1), pack2(h2, h3));
            *(uint2*)&sm[A_LO + r * RS + c] = make_uint2(pack2(q0, q1), pack2(q2, q3));
        }
        #pragma unroll
        for (int l = 0; l < BN * KC / 4 / 256; l++) {
            int i  = tid + l * 256;
            int n  = i % BN;
            int k0 = (i / BN) * 4;
            float v0 = W[(size_t)(kc * KC + k0 + 0) * BN + n];
            float v1 = W[(size_t)(kc * KC + k0 + 1) * BN + n];
            float v2 = W[(size_t)(kc * KC + k0 + 2) * BN + n];
            float v3 = W[(size_t)(kc * KC + k0 + 3) * BN + n];
            __half h0 = __float2half_rn(v0), h1 = __float2half_rn(v1);
            __half h2 = __float2half_rn(v2), h3 = __float2half_rn(v3);
            __half q0 = __float2half_rn(v0 - __half2float(h0));
            __half q1 = __float2half_rn(v1 - __half2float(h1));
            __half q2 = __float2half_rn(v2 - __half2float(h2));
            __half q3 = __float2half_rn(v3 - __half2float(h3));
            *(uint2*)&sm[B_HI + n * RS + k0] = make_uint2(pack2(h0, h1), pack2(h2, h3));
            *(uint2*)&sm[B_LO + n * RS + k0] = make_uint2(pack2(q0, q1), pack2(q2, q3));
        }
        __syncthreads();

        #pragma unroll
        for (int ks = 0; ks < KC / 16; ks++) {
            uint32_t ah[2][4], al[2][4];
            #pragma unroll
            for (int mt = 0; mt < 2; mt++) {
                uint32_t off = (uint32_t)((wm + mt * 16 + aRow) * RS + ks * 16 + aK) * 2;
                LDSM4(ah[mt], sb + A_HI * 2 + off);
                LDSM4(al[mt], sb + A_LO * 2 + off);
            }
            #pragma unroll
            for (int np = 0; np < NP; np++) {
                uint32_t bh[4], bl[4];
                uint32_t off = (uint32_t)((wn + np * 16 + bN) * RS + ks * 16 + bK) * 2;
                LDSM4(bh, sb + B_HI * 2 + off);
                LDSM4(bl, sb + B_LO * 2 + off);
                #pragma unroll
                for (int mt = 0; mt < 2; mt++) {
                    mma16816(acc[mt][np * 2 + 0], ah[mt], &bh[0]);
                    mma16816(acc[mt][np * 2 + 0], ah[mt], &bl[0]);
                    mma16816(acc[mt][np * 2 + 0], al[mt], &bh[0]);
                    mma16816(acc[mt][np * 2 + 1], ah[mt], &bh[2]);
                    mma16816(acc[mt][np * 2 + 1], ah[mt], &bl[2]);
                    mma16816(acc[mt][np * 2 + 1], al[mt], &bh[2]);
                }
            }
        }
        __syncthreads();
    }

    // ---- epilogue: rowwise absmax -> int16 quantize ----
    const int g  = lane >> 2;
    const int tg = lane & 3;
    const int wHalf = warp >> 2;
    float* redmax = (float*)sm;

    float pm[2][2];
    #pragma unroll
    for (int mt = 0; mt < 2; mt++) {
        float m0 = 0.f, m1 = 0.f;
        #pragma unroll
        for (int nt = 0; nt < NT; nt++) {
            m0 = fmaxf(m0, fmaxf(fabsf(acc[mt][nt][0]), fabsf(acc[mt][nt][1])));
            m1 = fmaxf(m1, fmaxf(fabsf(acc[mt][nt][2]), fabsf(acc[mt][nt][3])));
        }
        #pragma unroll
        for (int o = 1; o <= 2; o <<= 1) {
            m0 = fmaxf(m0, __shfl_xor_sync(0xFFFFFFFFu, m0, o));
            m1 = fmaxf(m1, __shfl_xor_sync(0xFFFFFFFFu, m1, o));
        }
        pm[mt][0] = m0; pm[mt][1] = m1;
    }
    if (tg == 0) {
        #pragma unroll
        for (int mt = 0; mt < 2; mt++) {
            redmax[wHalf * 128 + wm + mt * 16 + g]     = pm[mt][0];
            redmax[wHalf * 128 + wm + mt * 16 + g + 8] = pm[mt][1];
        }
    }
    __syncthreads();

    #pragma unroll
    for (int mt = 0; mt < 2; mt++) {
        #pragma unroll
        for (int h = 0; h < 2; h++) {
            int r  = wm + mt * 16 + g + h * 8;
            int gr = rowBase + r;
            float fm  = fmaxf(redmax[r], redmax[128 + r]);
            float inv = (fm > 0.f) ? 32766.0f / fm : 0.0f;
            if (gr < NN) {
                if (wHalf == 0 && tg == 0) SCL[gr] = fm * (1.0f / 32766.0f);
                #pragma unroll
                for (int nt = 0; nt < NT; nt++) {
                    int col = wn + nt * 8 + tg * 2;
                    short2 qq = make_short2(q16(acc[mt][nt][h * 2 + 0], inv),
                                            q16(acc[mt][nt][h * 2 + 1], inv));
                    *(short2*)&QT[(size_t)gr * BN + col] = qq;
                }
            }
        }
    }
}

// -------- Aggregation v3: warp = G independent nodes, branch-free body --------
// D=128: G=2 nodes/warp, 16 lanes each own a full 256B row slice (16B/lane).
// D=64 : G=4 nodes/warp,  8 lanes each own a full 128B row slice (16B/lane).
// No cross-group reduction; short-degree groups pad with zero-weight clamped
// loads (SEL/IMNMX only — the loop body is fully convergent).
template <int D, bool RELU>
__global__ void agg_kernel(const short* __restrict__ QT,
                           const float* __restrict__ SCL,
                           const float* __restrict__ bias,
                           float* __restrict__ out) {
    constexpr int L = (D == 128) ? 16 : 8;   // lanes per node
    constexpr int G = 32 / L;                // nodes per warp
    int wgl  = (blockIdx.x * blockDim.x + threadIdx.x) >> 5;
    int lane = threadIdx.x & 31;
    int part = lane / L;
    int sub  = lane % L;
    int node = wgl * G + part;
    if (wgl * G >= NN) return;               // whole warp out of range
    int nodeC = min(node, NN - 1);
    int beg = g_rowptr[nodeC];
    int cnt = g_rowptr[nodeC + 1] - beg;
    if (node >= NN) cnt = 0;

    int mc = cnt;                             // warp-wide max degree
    #pragma unroll
    for (int o = L; o < 32; o <<= 1)
        mc = max(mc, __shfl_xor_sync(0xFFFFFFFFu, mc, o));

    float acc[8];
    {   // self loop (uniform across all groups)
        float di = g_dinv[nodeC];
        float ws = di * di * SCL[nodeC];
        union { uint4 u; short s[8]; } q;
        q.u = *(const uint4*)(QT + (size_t)nodeC * D + sub * 8);
        #pragma unroll
        for (int k = 0; k < 8; k++) acc[k] = ws * (float)q.s[k];
    }

    int last = beg + max(cnt - 1, 0);
    for (int t = 0; t < mc; t++) {
        int je = min(min(beg + t, last), EE - 1);   // always-valid slot
        int2 e = g_edge[je];
        float w = (t < cnt) ? __int_as_float(e.y) : 0.0f;
        int src = e.x;                               // valid node id even when padded
        float ws = w * SCL[src];
        union { uint4 u; short s[8]; } q;
        q.u = *(const uint4*)(QT + (size_t)src * D + sub * 8);
        #pragma unroll
        for (int k = 0; k < 8; k++) acc[k] += ws * (float)q.s[k];
    }

    if (node < NN) {
        float4 b0 = *(const float4*)(bias + sub * 8);
        float4 b1 = *(const float4*)(bias + sub * 8 + 4);
        float4 o0 = make_float4(acc[0] + b0.x, acc[1] + b0.y, acc[2] + b0.z, acc[3] + b0.w);
        float4 o1 = make_float4(acc[4] + b1.x, acc[5] + b1.y, acc[6] + b1.z, acc[7] + b1.w);
        if (RELU) {
            o0.x = fmaxf(o0.x, 0.f); o0.y = fmaxf(o0.y, 0.f);
            o0.z = fmaxf(o0.z, 0.f); o0.w = fmaxf(o0.w, 0.f);
            o1.x = fmaxf(o1.x, 0.f); o1.y = fmaxf(o1.y, 0.f);
            o1.z = fmaxf(o1.z, 0.f); o1.w = fmaxf(o1.w, 0.f);
        }
        *(float4*)(out + (size_t)node * D + sub * 8)     = o0;
        *(float4*)(out + (size_t)node * D + sub * 8 + 4) = o1;
    }
}

// ---------------- launch ----------------
extern "C" void kernel_launch(void* const* d_in, const int* in_sizes, int n_in,
                              void* d_out, int out_size) {
    const float* x  = (const float*)d_in[0];
    const float* W0 = (const float*)d_in[1];
    const float* b0 = (const float*)d_in[2];
    const float* W1 = (const float*)d_in[3];
    const float* b1 = (const float*)d_in[4];
    const float* W2 = (const float*)d_in[5];
    const float* b2 = (const float*)d_in[6];
    const int*  src = (const int*)d_in[7];
    const int*  dst = (const int*)d_in[8];
    float* out = (float*)d_out;

    float *hbuf = nullptr, *scl = nullptr;
    short* qtab = nullptr;
    cudaGetSymbolAddress((void**)&hbuf, g_hbuf);
    cudaGetSymbolAddress((void**)&scl, g_scl);
    cudaGetSymbolAddress((void**)&qtab, g_qtab);

    static cudaStream_t sB = nullptr;
    static cudaEvent_t evFork = nullptr, evBuild = nullptr;
    if (sB == nullptr) {
        cudaStreamCreateWithFlags(&sB, cudaStreamNonBlocking);
        cudaEventCreateWithFlags(&evFork, cudaEventDisableTiming);
        cudaEventCreateWithFlags(&evBuild, cudaEventDisableTiming);
    }

    const int SMEM128 = (2 * 128 + 2 * 128) * 72 * 2;   // 73728
    const int SMEM64  = (2 * 128 + 2 * 64)  * 72 * 2;   // 55296
    cudaFuncSetAttribute(gemm_mma_kernel<128>,
                         cudaFuncAttributeMaxDynamicSharedMemorySize, SMEM128);
    cudaFuncSetAttribute(gemm_mma_kernel<64>,
                         cudaFuncAttributeMaxDynamicSharedMemorySize, SMEM64);

    const int TPB = 256;
    const int edgeBlocks = (EE + TPB - 1) / TPB;
    const int gemmBlocks = (NN + 127) / 128;
    const int aggBlocks128 = ((NN / 2) * 32 + TPB - 1) / TPB;   // 2 nodes/warp
    const int aggBlocks64  = ((NN / 4) * 32 + TPB - 1) / TPB;   // 4 nodes/warp

    // ---- fork: CSR build on sB, concurrent with gemm0 ----
    cudaEventRecord(evFork, 0);
    cudaStreamWaitEvent(sB, evFork, 0);

    count_deg_kernel<<<edgeBlocks, TPB, 0, sB>>>(dst);     // g_deg==0 invariant
    scan_local_kernel<<<SCAN_NBLK, SCAN_TPB, 0, sB>>>();   // + resets g_deg
    scan_add_kernel<<<SCAN_NBLK, SCAN_TPB, 0, sB>>>();     // scan_block fused in
    fill_csr_kernel<<<edgeBlocks, TPB, 0, sB>>>(src, dst);
    cudaEventRecord(evBuild, sB);

    gemm_mma_kernel<128><<<gemmBlocks, TPB, SMEM128>>>(x, W0, qtab, scl);

    cudaStreamWaitEvent(0, evBuild, 0);

    agg_kernel<128, true><<<aggBlocks128, TPB>>>(qtab, scl, b0, hbuf);
    gemm_mma_kernel<128><<<gemmBlocks, TPB, SMEM128>>>(hbuf, W1, qtab, scl);
    agg_kernel<128, true><<<aggBlocks128, TPB>>>(qtab, scl, b1, hbuf);
    gemm_mma_kernel<64><<<gemmBlocks, TPB, SMEM64>>>(hbuf, W2, qtab, scl);
    agg_kernel<64, false><<<aggBlocks64, TPB>>>(qtab, scl, b2, out);
}